// round 9
// baseline (speedup 1.0000x reference)
#include <cuda_runtime.h>
#include <math.h>
#include <stdint.h>

// Problem constants
#define BB   8
#define TT   512
#define DD   128
#define DLL  16
#define KK   8
#define HTH  32
#define NROWS (BB*TT)   // 4096
#define EPS2 0.0001f

// gelu Taylor: gelu(x) = 0.5x + C0 x^2 + C1 x^4 (|x| small)
#define C0g  0.3989422804014327f
#define C1g  (-0.06649038006690545f)

// Phi LUT: 2048 entries over dl2 in [0,16), step 1/128
#define LUTN   2048
#define LUTSCL 128.0f

// Scratch
__device__ __align__(16) float  g_l[2][NROWS*DLL];   // projected l vectors
__device__ __align__(16) float  g_PQ[2][NROWS*HTH];  // theta rank-1 vectors
__device__ float  g_hn[2][NROWS];
__device__ float  g_ln[2][NROWS];
__device__ float  g_c[2][NROWS];
__device__ __align__(16) float2 g_lut[LUTN];

// packed dual fp32 fma (sm_103a FFMA2)
#define FMA2(acc, av, bv) \
    asm("fma.rn.f32x2 %0, %1, %2, %0;" : "+l"(acc) : "l"(av), "l"(bv))

#define UNPK(lo, hi, v) \
    asm("mov.b64 {%0,%1}, %2;" : "=f"(lo), "=f"(hi) : "l"(v))

__device__ __forceinline__ unsigned long long dupf(float f) {
    unsigned long long d;
    asm("mov.b64 %0, {%1,%1};" : "=l"(d) : "f"(f));
    return d;
}

__device__ __forceinline__ unsigned long long packf(float lo, float hi) {
    unsigned long long d;
    asm("mov.b64 %0, {%1,%2};" : "=l"(d) : "f"(lo), "f"(hi));
    return d;
}

__device__ __forceinline__ float gelu_exact(float x) {
    return 0.5f * x * (1.0f + erff(x * 0.7071067811865475f));
}

// ---------------------------------------------------------------------------
// prep: grid (64, 3), block 128, dynamic smem.  (unchanged — known good)
// ---------------------------------------------------------------------------
#define P_SROW 0                       // 64 x 132
#define P_SWT  (P_SROW + 64*132)       // 24 x 132 (transposed weights)
#define P_SL   (P_SWT  + 24*132)       // 64 x 20
#define P_STH  (P_SL   + 64*20)        // 64 x 12
#define P_SCW  (P_STH  + 64*12)        // 8 x 32
#define PREP_SMEM ((P_SCW + 256) * 4)

__global__ __launch_bounds__(128)
void prep_kernel(const float* __restrict__ h,
                 const float* __restrict__ hsrc,
                 const float* __restrict__ W_l,
                 const float* __restrict__ W_theta,
                 const float* __restrict__ wq,
                 const float* __restrict__ ws,
                 const float* __restrict__ wd,
                 const float* __restrict__ b1,
                 const float* __restrict__ w2_w,
                 const float* __restrict__ phi1_w,
                 const float* __restrict__ phi1_b,
                 const float* __restrict__ phi2_w,
                 const float* __restrict__ phi2_b)
{
    int side = blockIdx.y;
    int tid  = threadIdx.x;

    if (side == 2) {
        int wid = tid >> 5, lane = tid & 31;
        float w = phi1_w[lane], b = phi1_b[lane], v = phi2_w[lane];
        float ph2b = phi2_b[0];
        #pragma unroll
        for (int sub = 0; sub < 8; sub++) {
            int e = blockIdx.x * 32 + wid * 8 + sub;
            float x0 = (float)e       * (1.0f / LUTSCL);
            float x1 = (float)(e + 1) * (1.0f / LUTSCL);
            float s0 = gelu_exact(fmaf(x0, w, b)) * v;
            float s1 = gelu_exact(fmaf(x1, w, b)) * v;
            #pragma unroll
            for (int o = 16; o > 0; o >>= 1) {
                s0 += __shfl_xor_sync(0xffffffffu, s0, o);
                s1 += __shfl_xor_sync(0xffffffffu, s1, o);
            }
            if (lane == 0) {
                float a0 = s0 + ph2b, a1 = s1 + ph2b;
                float c0 = fmaxf(a0, 0.f) + log1pf(expf(-fabsf(a0)));
                float c1 = fmaxf(a1, 0.f) + log1pf(expf(-fabsf(a1)));
                float p0 = expf(-c0 * x0);
                float p1 = expf(-c1 * x1);
                g_lut[e] = make_float2(p0, p1 - p0);
            }
        }
        return;
    }

    extern __shared__ float ps[];
    float* SROW = ps + P_SROW;
    float* SWT  = ps + P_SWT;
    float* SL   = ps + P_SL;
    float* STH  = ps + P_STH;
    float* SCW  = ps + P_SCW;

    int r0 = blockIdx.x * 64;
    const float* src = (side == 0) ? h : hsrc;

    {
        const float4* sv = (const float4*)(src + (size_t)r0 * DD);
        #pragma unroll
        for (int i = 0; i < 16; i++) {
            int idx = tid + i * 128;
            int r = idx >> 5, c4 = idx & 31;
            *(float4*)(SROW + r * 132 + c4 * 4) = sv[r * 32 + c4];
        }
        #pragma unroll
        for (int i = 0; i < 16; i++) {
            int idx = tid + i * 128;
            int c = idx & 15, d = idx >> 4;
            SWT[c * 132 + d] = W_l[d * DLL + c];
        }
        #pragma unroll
        for (int i = 0; i < 8; i++) {
            int idx = tid + i * 128;
            int c = idx & 7, d = idx >> 3;
            SWT[(16 + c) * 132 + d] = W_theta[d * KK + c];
        }
        #pragma unroll
        for (int i = 0; i < 2; i++) {
            int idx = tid + i * 128;
            float a = wq[idx], s = ws[idx], d = wd[idx];
            SCW[idx] = (side == 0) ? (a + d) : (s - d);
        }
    }
    __syncthreads();

    {
        int rg = tid >> 3, cg = tid & 7;
        float acc[4][3];
        #pragma unroll
        for (int i = 0; i < 4; i++)
            #pragma unroll
            for (int j = 0; j < 3; j++) acc[i][j] = 0.f;

        const float* sr = SROW + (rg * 4) * 132;
        #pragma unroll 4
        for (int kc = 0; kc < 32; kc++) {
            float4 x[4], w[3];
            #pragma unroll
            for (int i = 0; i < 4; i++)
                x[i] = *(const float4*)(sr + i * 132 + kc * 4);
            #pragma unroll
            for (int j = 0; j < 3; j++)
                w[j] = *(const float4*)(SWT + (cg + 8 * j) * 132 + kc * 4);
            #pragma unroll
            for (int i = 0; i < 4; i++)
                #pragma unroll
                for (int j = 0; j < 3; j++) {
                    acc[i][j] = fmaf(x[i].x, w[j].x, acc[i][j]);
                    acc[i][j] = fmaf(x[i].y, w[j].y, acc[i][j]);
                    acc[i][j] = fmaf(x[i].z, w[j].z, acc[i][j]);
                    acc[i][j] = fmaf(x[i].w, w[j].w, acc[i][j]);
                }
        }
        #pragma unroll
        for (int i = 0; i < 4; i++)
            #pragma unroll
            for (int j = 0; j < 3; j++) {
                int r = rg * 4 + i, c = cg + 8 * j;
                if (c < DLL) {
                    SL[r * 20 + c] = acc[i][j];
                    g_l[side][(size_t)(r0 + r) * DLL + c] = acc[i][j];
                } else {
                    STH[r * 12 + (c - 16)] = acc[i][j];
                }
            }
    }
    __syncthreads();

    {
        int r = tid >> 1, half = tid & 1;
        const float* sr = SROW + r * 132 + half * 64;
        float a = 0.f;
        #pragma unroll
        for (int c4 = 0; c4 < 16; c4++) {
            float4 x = *(const float4*)(sr + c4 * 4);
            a = fmaf(x.x, x.x, a); a = fmaf(x.y, x.y, a);
            a = fmaf(x.z, x.z, a); a = fmaf(x.w, x.w, a);
        }
        a += __shfl_xor_sync(0xffffffffu, a, 1);
        if (half == 0) g_hn[side][r0 + r] = a;
    }
    if (tid < 64) {
        const float* sr = SL + tid * 20;
        float a = 0.f;
        #pragma unroll
        for (int c4 = 0; c4 < 4; c4++) {
            float4 x = *(const float4*)(sr + c4 * 4);
            a = fmaf(x.x, x.x, a); a = fmaf(x.y, x.y, a);
            a = fmaf(x.z, x.z, a); a = fmaf(x.w, x.w, a);
        }
        g_ln[side][r0 + tid] = a;
    }

    #pragma unroll
    for (int i = 0; i < 16; i++) {
        int idx = tid + i * 128;
        int r = idx >> 5, c = idx & 31;
        float x = (side == 0) ? __ldg(&b1[c]) : 0.f;
        #pragma unroll
        for (int k = 0; k < KK; k++)
            x = fmaf(STH[r * 12 + k], SCW[k * HTH + c], x);
        float w2 = __ldg(&w2_w[c]);
        float x2 = x * x;
        g_PQ[side][(size_t)(r0 + r) * HTH + c] =
            (side == 0) ? (2.0f * C0g * w2 * x) : x;
        float v = w2 * (fmaf(C1g, x2 * x2, fmaf(C0g, x2, 0.5f * x)));
        #pragma unroll
        for (int o = 16; o > 0; o >>= 1)
            v += __shfl_xor_sync(0xffffffffu, v, o);
        if (c == 0) g_c[side][r0 + r] = v;
    }
}

// ---------------------------------------------------------------------------
// main: 128x128 tile, 256 thr, 8x8 micro-tile with PACKED-J accumulators.
// Tiles stored [k][row] in smem (transposed, stride 132).
// Phase A: theta (K=32) + l (K=16) -> writes -Theta*Phi to out.
// Phase B: h Gram (K=128, two K=64 halves reusing the X region) -> out *= 1/r.
// ---------------------------------------------------------------------------
// float offsets in dynamic smem
#define X_PQT 0                      // 32 x 132
#define X_PQS (32*132)               // 4224
#define X_LT  (2*32*132)             // 8448: 16 x 132
#define X_LS  (X_LT + 16*132)
#define X_HT  0                      // 64 x 132 (phase B)
#define X_HS  (64*132)               // 8448
#define M_SC  (2*64*132)             // 16896
#define MAIN_SMEM ((M_SC + 768) * 4)

__global__ __launch_bounds__(256)
void main_kernel(const float* __restrict__ h, const float* __restrict__ hsrc,
                 const float* __restrict__ w2_b, float* __restrict__ out)
{
    extern __shared__ float S[];
    float* sc = S + M_SC;
    // sc: [0]=hn_t [128]=hn_s [256]=ln_t [384]=ln_s [512]=c_t [640]=c_s

    int bz  = blockIdx.z;
    int t0  = blockIdx.y * 128;
    int s0  = blockIdx.x * 128;
    int tid = threadIdx.x;
    int rt  = bz * TT + t0;
    int rs  = bz * TT + s0;

    int i0 = (tid >> 4) * 8;    // 8 t-rows
    int j0 = (tid & 15) * 8;    // 8 s-cols

    // ============== stage phase-A tiles (transposed [k][row]) ==============
    {
        const float4* pt = (const float4*)(g_PQ[0] + (size_t)rt * HTH);
        const float4* qs = (const float4*)(g_PQ[1] + (size_t)rs * HTH);
        #pragma unroll
        for (int it = 0; it < 4; it++) {
            int idx = tid + it * 256;       // < 1024
            int i = idx & 127, kc = idx >> 7;   // kc 0..7
            float4 v = pt[i * 8 + kc];
            S[X_PQT + (kc * 4 + 0) * 132 + i] = v.x;
            S[X_PQT + (kc * 4 + 1) * 132 + i] = v.y;
            S[X_PQT + (kc * 4 + 2) * 132 + i] = v.z;
            S[X_PQT + (kc * 4 + 3) * 132 + i] = v.w;
            float4 u = qs[i * 8 + kc];
            S[X_PQS + (kc * 4 + 0) * 132 + i] = u.x;
            S[X_PQS + (kc * 4 + 1) * 132 + i] = u.y;
            S[X_PQS + (kc * 4 + 2) * 132 + i] = u.z;
            S[X_PQS + (kc * 4 + 3) * 132 + i] = u.w;
        }
        const float4* lt = (const float4*)(g_l[0] + (size_t)rt * DLL);
        const float4* ls = (const float4*)(g_l[1] + (size_t)rs * DLL);
        #pragma unroll
        for (int it = 0; it < 2; it++) {
            int idx = tid + it * 256;       // < 512
            int i = idx & 127, kc = idx >> 7;   // kc 0..3
            float4 v = lt[i * 4 + kc];
            S[X_LT + (kc * 4 + 0) * 132 + i] = v.x;
            S[X_LT + (kc * 4 + 1) * 132 + i] = v.y;
            S[X_LT + (kc * 4 + 2) * 132 + i] = v.z;
            S[X_LT + (kc * 4 + 3) * 132 + i] = v.w;
            float4 u = ls[i * 4 + kc];
            S[X_LS + (kc * 4 + 0) * 132 + i] = u.x;
            S[X_LS + (kc * 4 + 1) * 132 + i] = u.y;
            S[X_LS + (kc * 4 + 2) * 132 + i] = u.z;
            S[X_LS + (kc * 4 + 3) * 132 + i] = u.w;
        }
        if (tid < 128) {
            sc[tid]       = g_hn[0][rt + tid];
            sc[128 + tid] = g_hn[1][rs + tid];
            sc[256 + tid] = g_ln[0][rt + tid];
            sc[384 + tid] = g_ln[1][rs + tid];
            sc[512 + tid] = g_c [0][rt + tid];
            sc[640 + tid] = g_c [1][rs + tid];
        }
    }
    float w2b = __ldg(w2_b);
    __syncthreads();

    unsigned long long acc[32], acc2[32];

    // ============== theta dot (K=32), packed-j ==============
    #pragma unroll
    for (int q = 0; q < 32; q++) acc[q] = 0ull;
    #pragma unroll 4
    for (int k = 0; k < 32; k++) {
        const float* ra = S + X_PQT + k * 132 + i0;
        const float* rb = S + X_PQS + k * 132 + j0;
        float4 aA = *(const float4*)ra;
        float4 aB = *(const float4*)(ra + 4);
        ulonglong2 b0 = *(const ulonglong2*)rb;
        ulonglong2 b1 = *(const ulonglong2*)(rb + 4);
        unsigned long long ad[8] = {
            dupf(aA.x), dupf(aA.y), dupf(aA.z), dupf(aA.w),
            dupf(aB.x), dupf(aB.y), dupf(aB.z), dupf(aB.w) };
        #pragma unroll
        for (int ii = 0; ii < 8; ii++) {
            FMA2(acc[ii * 4 + 0], ad[ii], b0.x);
            FMA2(acc[ii * 4 + 1], ad[ii], b0.y);
            FMA2(acc[ii * 4 + 2], ad[ii], b1.x);
            FMA2(acc[ii * 4 + 3], ad[ii], b1.y);
        }
    }
    // convert in place: acc[q] := packed(-Theta0, -Theta1)
    #pragma unroll
    for (int ii = 0; ii < 8; ii++) {
        float ct = sc[512 + i0 + ii];
        #pragma unroll
        for (int jp = 0; jp < 4; jp++) {
            float d0, d1;
            UNPK(d0, d1, acc[ii * 4 + jp]);
            float a0 = w2b + ct + sc[640 + j0 + 2 * jp]     + d0;
            float a1 = w2b + ct + sc[640 + j0 + 2 * jp + 1] + d1;
            float u0 = a0 * a0, u1 = a1 * a1;
            float T0 = a0 * fmaf(u0, fmaf(u0, fmaf(u0, -0.05396825397f,
                                   0.13333333333f), -0.33333333333f), 1.0f);
            float T1 = a1 * fmaf(u1, fmaf(u1, fmaf(u1, -0.05396825397f,
                                   0.13333333333f), -0.33333333333f), 1.0f);
            acc[ii * 4 + jp] = packf(-T0, -T1);
        }
    }

    // ============== l dot (K=16), packed-j ==============
    #pragma unroll
    for (int q = 0; q < 32; q++) acc2[q] = 0ull;
    #pragma unroll 4
    for (int k = 0; k < 16; k++) {
        const float* ra = S + X_LT + k * 132 + i0;
        const float* rb = S + X_LS + k * 132 + j0;
        float4 aA = *(const float4*)ra;
        float4 aB = *(const float4*)(ra + 4);
        ulonglong2 b0 = *(const ulonglong2*)rb;
        ulonglong2 b1 = *(const ulonglong2*)(rb + 4);
        unsigned long long ad[8] = {
            dupf(aA.x), dupf(aA.y), dupf(aA.z), dupf(aA.w),
            dupf(aB.x), dupf(aB.y), dupf(aB.z), dupf(aB.w) };
        #pragma unroll
        for (int ii = 0; ii < 8; ii++) {
            FMA2(acc2[ii * 4 + 0], ad[ii], b0.x);
            FMA2(acc2[ii * 4 + 1], ad[ii], b0.y);
            FMA2(acc2[ii * 4 + 2], ad[ii], b1.x);
            FMA2(acc2[ii * 4 + 3], ad[ii], b1.y);
        }
    }
    // combine: out = -Theta * Phi
    #pragma unroll
    for (int ii = 0; ii < 8; ii++) {
        float lnt = sc[256 + i0 + ii];
        size_t orow = ((size_t)(bz * TT + t0 + i0 + ii)) * TT + s0 + j0;
        float v[8];
        #pragma unroll
        for (int jp = 0; jp < 4; jp++) {
            float e0, e1, m0, m1;
            UNPK(e0, e1, acc2[ii * 4 + jp]);
            UNPK(m0, m1, acc[ii * 4 + jp]);
            float dl20 = fmaxf(fmaf(-2.f, e0, lnt + sc[384 + j0 + 2 * jp]), 0.f);
            float dl21 = fmaxf(fmaf(-2.f, e1, lnt + sc[384 + j0 + 2 * jp + 1]), 0.f);
            float t0 = fminf(dl20 * LUTSCL, (float)(LUTN - 1));
            float t1 = fminf(dl21 * LUTSCL, (float)(LUTN - 1));
            int   x0 = (int)t0, x1 = (int)t1;
            float2 l0 = __ldg(&g_lut[x0]);
            float2 l1 = __ldg(&g_lut[x1]);
            v[2 * jp]     = m0 * fmaf(t0 - (float)x0, l0.y, l0.x);
            v[2 * jp + 1] = m1 * fmaf(t1 - (float)x1, l1.y, l1.x);
        }
        *(float4*)(out + orow)     = make_float4(v[0], v[1], v[2], v[3]);
        *(float4*)(out + orow + 4) = make_float4(v[4], v[5], v[6], v[7]);
    }

    // ============== h Gram (K=128, two K=64 halves) ==============
    #pragma unroll
    for (int q = 0; q < 32; q++) acc[q] = 0ull;

    for (int kh = 0; kh < 2; kh++) {
        __syncthreads();    // X region handoff
        {
            const float4* tv = (const float4*)(h    + (size_t)rt * DD + kh * 64);
            const float4* sv = (const float4*)(hsrc + (size_t)rs * DD + kh * 64);
            #pragma unroll
            for (int it = 0; it < 8; it++) {
                int idx = tid + it * 256;   // < 2048
                int i = idx & 127, kc = idx >> 7;   // kc 0..15
                float4 v = tv[i * 32 + kc];
                S[X_HT + (kc * 4 + 0) * 132 + i] = v.x;
                S[X_HT + (kc * 4 + 1) * 132 + i] = v.y;
                S[X_HT + (kc * 4 + 2) * 132 + i] = v.z;
                S[X_HT + (kc * 4 + 3) * 132 + i] = v.w;
                float4 u = sv[i * 32 + kc];
                S[X_HS + (kc * 4 + 0) * 132 + i] = u.x;
                S[X_HS + (kc * 4 + 1) * 132 + i] = u.y;
                S[X_HS + (kc * 4 + 2) * 132 + i] = u.z;
                S[X_HS + (kc * 4 + 3) * 132 + i] = u.w;
            }
        }
        __syncthreads();

        #pragma unroll 4
        for (int k = 0; k < 64; k++) {
            const float* ra = S + X_HT + k * 132 + i0;
            const float* rb = S + X_HS + k * 132 + j0;
            float4 aA = *(const float4*)ra;
            float4 aB = *(const float4*)(ra + 4);
            ulonglong2 b0 = *(const ulonglong2*)rb;
            ulonglong2 b1 = *(const ulonglong2*)(rb + 4);
            unsigned long long ad[8] = {
                dupf(aA.x), dupf(aA.y), dupf(aA.z), dupf(aA.w),
                dupf(aB.x), dupf(aB.y), dupf(aB.z), dupf(aB.w) };
            #pragma unroll
            for (int ii = 0; ii < 8; ii++) {
                FMA2(acc[ii * 4 + 0], ad[ii], b0.x);
                FMA2(acc[ii * 4 + 1], ad[ii], b0.y);
                FMA2(acc[ii * 4 + 2], ad[ii], b1.x);
                FMA2(acc[ii * 4 + 3], ad[ii], b1.y);
            }
        }
    }

    // ============== epilogue: out *= 1/r ==============
    {
        float4 hsa = *(const float4*)(sc + 128 + j0);
        float4 hsb = *(const float4*)(sc + 128 + j0 + 4);
        float hns[8] = { hsa.x, hsa.y, hsa.z, hsa.w,
                         hsb.x, hsb.y, hsb.z, hsb.w };
        #pragma unroll
        for (int ii = 0; ii < 8; ii++) {
            float hnt = sc[i0 + ii];
            size_t orow = ((size_t)(bz * TT + t0 + i0 + ii)) * TT + s0 + j0;
            float4 ta = *(const float4*)(out + orow);
            float4 tb = *(const float4*)(out + orow + 4);
            float tp[8] = { ta.x, ta.y, ta.z, ta.w, tb.x, tb.y, tb.z, tb.w };
            float v[8];
            #pragma unroll
            for (int jp = 0; jp < 4; jp++) {
                float d0, d1;
                UNPK(d0, d1, acc[ii * 4 + jp]);
                float dh0 = fmaxf(fmaf(-2.f, d0, hnt + hns[2 * jp]),     0.f) + EPS2;
                float dh1 = fmaxf(fmaf(-2.f, d1, hnt + hns[2 * jp + 1]), 0.f) + EPS2;
                v[2 * jp]     = tp[2 * jp]     * rsqrtf(dh0);
                v[2 * jp + 1] = tp[2 * jp + 1] * rsqrtf(dh1);
            }
            *(float4*)(out + orow)     = make_float4(v[0], v[1], v[2], v[3]);
            *(float4*)(out + orow + 4) = make_float4(v[4], v[5], v[6], v[7]);
        }
    }
}

// ---------------------------------------------------------------------------
extern "C" void kernel_launch(void* const* d_in, const int* in_sizes, int n_in,
                              void* d_out, int out_size)
{
    (void)in_sizes; (void)n_in; (void)out_size;
    const float* h       = (const float*)d_in[0];
    const float* hsrc    = (const float*)d_in[1];
    const float* W_l     = (const float*)d_in[2];
    const float* W_theta = (const float*)d_in[3];
    const float* phi1_w  = (const float*)d_in[4];
    const float* phi1_b  = (const float*)d_in[5];
    const float* phi2_w  = (const float*)d_in[6];
    const float* phi2_b  = (const float*)d_in[7];
    const float* wq      = (const float*)d_in[8];
    const float* ws      = (const float*)d_in[9];
    const float* wd      = (const float*)d_in[10];
    const float* b1      = (const float*)d_in[11];
    const float* w2_w    = (const float*)d_in[12];
    const float* w2_b    = (const float*)d_in[13];
    float* out = (float*)d_out;

    cudaFuncSetAttribute(prep_kernel,
                         cudaFuncAttributeMaxDynamicSharedMemorySize, PREP_SMEM);
    cudaFuncSetAttribute(main_kernel,
                         cudaFuncAttributeMaxDynamicSharedMemorySize, MAIN_SMEM);

    prep_kernel<<<dim3(64, 3), 128, PREP_SMEM>>>(h, hsrc, W_l, W_theta,
                                                 wq, ws, wd, b1, w2_w,
                                                 phi1_w, phi1_b, phi2_w, phi2_b);
    main_kernel<<<dim3(4, 4, BB), 256, MAIN_SMEM>>>(h, hsrc, w2_b, out);
}

// round 10
// speedup vs baseline: 1.8091x; 1.8091x over previous
#include <cuda_runtime.h>
#include <math.h>
#include <stdint.h>

// Problem constants
#define BB   8
#define TT   512
#define DD   128
#define DLL  16
#define KK   8
#define HTH  32
#define NROWS (BB*TT)   // 4096
#define EPS2 0.0001f

// gelu Taylor: gelu(x) = 0.5x + C0 x^2 + C1 x^4 (|x| small)
#define C0g  0.3989422804014327f
#define C1g  (-0.06649038006690545f)

// Phi LUT: 2048 entries over dl2 in [0,16), step 1/128
#define LUTN   2048
#define LUTSCL 128.0f

// Scratch
__device__ __align__(16) float  g_l[2][NROWS*DLL];   // projected l vectors (tf32-rounded)
__device__ __align__(16) float  g_PQ[2][NROWS*HTH];  // theta rank-1 vectors (tf32-rounded)
__device__ float  g_hn[2][NROWS];
__device__ float  g_ln[2][NROWS];
__device__ float  g_c[2][NROWS];
__device__ __align__(16) float2 g_lut[LUTN];

// ---------------------------------------------------------------------------
// helpers
// ---------------------------------------------------------------------------
__device__ __forceinline__ float tf32r(float x) {
    unsigned u;
    asm("cvt.rna.tf32.f32 %0, %1;" : "=r"(u) : "f"(x));
    return __uint_as_float(u);
}

// m16n8k8 tf32 MMA, fp32 accumulate (sm_80 PTX -> Blackwell HMMA)
__device__ __forceinline__ void mma8(float* d, const unsigned* a, const unsigned* b) {
    asm volatile(
        "mma.sync.aligned.m16n8k8.row.col.f32.tf32.tf32.f32 "
        "{%0,%1,%2,%3},{%4,%5,%6,%7},{%8,%9},{%0,%1,%2,%3};"
        : "+f"(d[0]), "+f"(d[1]), "+f"(d[2]), "+f"(d[3])
        : "r"(a[0]), "r"(a[1]), "r"(a[2]), "r"(a[3]), "r"(b[0]), "r"(b[1]));
}

__device__ __forceinline__ unsigned ldsu(const float* p) {
    return __float_as_uint(*p);
}

__device__ __forceinline__ float gelu_exact(float x) {
    return 0.5f * x * (1.0f + erff(x * 0.7071067811865475f));
}

// ---------------------------------------------------------------------------
// prep: grid (64, 3), block 128, dynamic smem. (R6 structure + tf32 rounding)
// ---------------------------------------------------------------------------
#define P_SROW 0                       // 64 x 132
#define P_SWT  (P_SROW + 64*132)       // 24 x 132 (transposed weights)
#define P_SL   (P_SWT  + 24*132)       // 64 x 20
#define P_STH  (P_SL   + 64*20)        // 64 x 12
#define P_SCW  (P_STH  + 64*12)        // 8 x 32
#define PREP_SMEM ((P_SCW + 256) * 4)

__global__ __launch_bounds__(128)
void prep_kernel(const float* __restrict__ h,
                 const float* __restrict__ hsrc,
                 const float* __restrict__ W_l,
                 const float* __restrict__ W_theta,
                 const float* __restrict__ wq,
                 const float* __restrict__ ws,
                 const float* __restrict__ wd,
                 const float* __restrict__ b1,
                 const float* __restrict__ w2_w,
                 const float* __restrict__ phi1_w,
                 const float* __restrict__ phi1_b,
                 const float* __restrict__ phi2_w,
                 const float* __restrict__ phi2_b)
{
    int side = blockIdx.y;
    int tid  = threadIdx.x;

    if (side == 2) {
        int wid = tid >> 5, lane = tid & 31;
        float w = phi1_w[lane], b = phi1_b[lane], v = phi2_w[lane];
        float ph2b = phi2_b[0];
        #pragma unroll
        for (int sub = 0; sub < 8; sub++) {
            int e = blockIdx.x * 32 + wid * 8 + sub;
            float x0 = (float)e       * (1.0f / LUTSCL);
            float x1 = (float)(e + 1) * (1.0f / LUTSCL);
            float s0 = gelu_exact(fmaf(x0, w, b)) * v;
            float s1 = gelu_exact(fmaf(x1, w, b)) * v;
            #pragma unroll
            for (int o = 16; o > 0; o >>= 1) {
                s0 += __shfl_xor_sync(0xffffffffu, s0, o);
                s1 += __shfl_xor_sync(0xffffffffu, s1, o);
            }
            if (lane == 0) {
                float a0 = s0 + ph2b, a1 = s1 + ph2b;
                float c0 = fmaxf(a0, 0.f) + log1pf(expf(-fabsf(a0)));
                float c1 = fmaxf(a1, 0.f) + log1pf(expf(-fabsf(a1)));
                float p0 = expf(-c0 * x0);
                float p1 = expf(-c1 * x1);
                g_lut[e] = make_float2(p0, p1 - p0);
            }
        }
        return;
    }

    extern __shared__ float ps[];
    float* SROW = ps + P_SROW;
    float* SWT  = ps + P_SWT;
    float* SL   = ps + P_SL;
    float* STH  = ps + P_STH;
    float* SCW  = ps + P_SCW;

    int r0 = blockIdx.x * 64;
    const float* src = (side == 0) ? h : hsrc;

    {
        const float4* sv = (const float4*)(src + (size_t)r0 * DD);
        #pragma unroll
        for (int i = 0; i < 16; i++) {
            int idx = tid + i * 128;
            int r = idx >> 5, c4 = idx & 31;
            *(float4*)(SROW + r * 132 + c4 * 4) = sv[r * 32 + c4];
        }
        #pragma unroll
        for (int i = 0; i < 16; i++) {
            int idx = tid + i * 128;
            int c = idx & 15, d = idx >> 4;
            SWT[c * 132 + d] = W_l[d * DLL + c];
        }
        #pragma unroll
        for (int i = 0; i < 8; i++) {
            int idx = tid + i * 128;
            int c = idx & 7, d = idx >> 3;
            SWT[(16 + c) * 132 + d] = W_theta[d * KK + c];
        }
        #pragma unroll
        for (int i = 0; i < 2; i++) {
            int idx = tid + i * 128;
            float a = wq[idx], s = ws[idx], d = wd[idx];
            SCW[idx] = (side == 0) ? (a + d) : (s - d);
        }
    }
    __syncthreads();

    {
        int rg = tid >> 3, cg = tid & 7;
        float acc[4][3];
        #pragma unroll
        for (int i = 0; i < 4; i++)
            #pragma unroll
            for (int j = 0; j < 3; j++) acc[i][j] = 0.f;

        const float* sr = SROW + (rg * 4) * 132;
        #pragma unroll 4
        for (int kc = 0; kc < 32; kc++) {
            float4 x[4], w[3];
            #pragma unroll
            for (int i = 0; i < 4; i++)
                x[i] = *(const float4*)(sr + i * 132 + kc * 4);
            #pragma unroll
            for (int j = 0; j < 3; j++)
                w[j] = *(const float4*)(SWT + (cg + 8 * j) * 132 + kc * 4);
            #pragma unroll
            for (int i = 0; i < 4; i++)
                #pragma unroll
                for (int j = 0; j < 3; j++) {
                    acc[i][j] = fmaf(x[i].x, w[j].x, acc[i][j]);
                    acc[i][j] = fmaf(x[i].y, w[j].y, acc[i][j]);
                    acc[i][j] = fmaf(x[i].z, w[j].z, acc[i][j]);
                    acc[i][j] = fmaf(x[i].w, w[j].w, acc[i][j]);
                }
        }
        #pragma unroll
        for (int i = 0; i < 4; i++)
            #pragma unroll
            for (int j = 0; j < 3; j++) {
                int r = rg * 4 + i, c = cg + 8 * j;
                if (c < DLL) {
                    float lr = tf32r(acc[i][j]);   // round so ln is consistent
                    SL[r * 20 + c] = lr;
                    g_l[side][(size_t)(r0 + r) * DLL + c] = lr;
                } else {
                    STH[r * 12 + (c - 16)] = acc[i][j];
                }
            }
    }
    __syncthreads();

    {
        // hn from tf32-rounded h (consistent with main's Gram inputs)
        int r = tid >> 1, half = tid & 1;
        const float* sr = SROW + r * 132 + half * 64;
        float a = 0.f;
        #pragma unroll
        for (int c4 = 0; c4 < 16; c4++) {
            float4 x = *(const float4*)(sr + c4 * 4);
            float x0 = tf32r(x.x), x1 = tf32r(x.y);
            float x2 = tf32r(x.z), x3 = tf32r(x.w);
            a = fmaf(x0, x0, a); a = fmaf(x1, x1, a);
            a = fmaf(x2, x2, a); a = fmaf(x3, x3, a);
        }
        a += __shfl_xor_sync(0xffffffffu, a, 1);
        if (half == 0) g_hn[side][r0 + r] = a;
    }
    if (tid < 64) {
        const float* sr = SL + tid * 20;
        float a = 0.f;
        #pragma unroll
        for (int c4 = 0; c4 < 4; c4++) {
            float4 x = *(const float4*)(sr + c4 * 4);
            a = fmaf(x.x, x.x, a); a = fmaf(x.y, x.y, a);
            a = fmaf(x.z, x.z, a); a = fmaf(x.w, x.w, a);
        }
        g_ln[side][r0 + tid] = a;
    }

    #pragma unroll
    for (int i = 0; i < 16; i++) {
        int idx = tid + i * 128;
        int r = idx >> 5, c = idx & 31;
        float x = (side == 0) ? __ldg(&b1[c]) : 0.f;
        #pragma unroll
        for (int k = 0; k < KK; k++)
            x = fmaf(STH[r * 12 + k], SCW[k * HTH + c], x);
        float w2 = __ldg(&w2_w[c]);
        float x2 = x * x;
        g_PQ[side][(size_t)(r0 + r) * HTH + c] =
            tf32r((side == 0) ? (2.0f * C0g * w2 * x) : x);
        float v = w2 * (fmaf(C1g, x2 * x2, fmaf(C0g, x2, 0.5f * x)));
        #pragma unroll
        for (int o = 16; o > 0; o >>= 1)
            v += __shfl_xor_sync(0xffffffffu, v, o);
        if (c == 0) g_c[side][r0 + r] = v;
    }
}

// ---------------------------------------------------------------------------
// main: 128x128 tile, 8 warps; warp = 16x128 strip; m16n8k8 tf32 mma for all
// three Grams. Phase A: theta+l -> tp[16][4] regs. Phase B: h Gram -> acc.
// ---------------------------------------------------------------------------
// float offsets in dynamic smem
#define S_HT  0                        // 128 x 132
#define S_HS  (S_HT  + 128*132)
#define S_PT  (S_HS  + 128*132)        // 128 x 36
#define S_QS  (S_PT  + 128*36)
#define S_LT  (S_QS  + 128*36)         // 128 x 20
#define S_LS  (S_LT  + 128*20)
#define S_LUT (S_LS  + 128*20)         // 2048 float2
#define S_SC  (S_LUT + 4096)           // 768
#define MAIN_SMEM ((S_SC + 768) * 4)

__global__ __launch_bounds__(256)
void main_kernel(const float* __restrict__ h, const float* __restrict__ hsrc,
                 const float* __restrict__ w2_b, float* __restrict__ out)
{
    extern __shared__ float S[];
    float* sc = S + S_SC;
    // sc: [0]=hn_t [128]=hn_s [256]=ln_t [384]=ln_s [512]=c_t [640]=c_s

    int bz  = blockIdx.z;
    int t0  = blockIdx.y * 128;
    int s0  = blockIdx.x * 128;
    int tid = threadIdx.x;
    int rt  = bz * TT + t0;
    int rs  = bz * TT + s0;

    // ================= stage =================
    {
        const float4* tv = (const float4*)(h    + (size_t)rt * DD);
        const float4* sv = (const float4*)(hsrc + (size_t)rs * DD);
        #pragma unroll
        for (int i = 0; i < 16; i++) {
            int idx = tid + i * 256;        // < 4096
            int r = idx >> 5, c4 = idx & 31;
            float4 a = tv[r * 32 + c4];
            a.x = tf32r(a.x); a.y = tf32r(a.y); a.z = tf32r(a.z); a.w = tf32r(a.w);
            *(float4*)(S + S_HT + r * 132 + c4 * 4) = a;
            float4 b = sv[r * 32 + c4];
            b.x = tf32r(b.x); b.y = tf32r(b.y); b.z = tf32r(b.z); b.w = tf32r(b.w);
            *(float4*)(S + S_HS + r * 132 + c4 * 4) = b;
        }
        const float4* pt = (const float4*)(g_PQ[0] + (size_t)rt * HTH);
        const float4* qs = (const float4*)(g_PQ[1] + (size_t)rs * HTH);
        #pragma unroll
        for (int i = 0; i < 4; i++) {
            int idx = tid + i * 256;        // < 1024
            int r = idx >> 3, c4 = idx & 7;
            *(float4*)(S + S_PT + r * 36 + c4 * 4) = pt[r * 8 + c4];
            *(float4*)(S + S_QS + r * 36 + c4 * 4) = qs[r * 8 + c4];
        }
        const float4* lt = (const float4*)(g_l[0] + (size_t)rt * DLL);
        const float4* ls = (const float4*)(g_l[1] + (size_t)rs * DLL);
        #pragma unroll
        for (int i = 0; i < 2; i++) {
            int idx = tid + i * 256;        // < 512
            int r = idx >> 2, c4 = idx & 3;
            *(float4*)(S + S_LT + r * 20 + c4 * 4) = lt[r * 4 + c4];
            *(float4*)(S + S_LS + r * 20 + c4 * 4) = ls[r * 4 + c4];
        }
        const float4* lv = (const float4*)g_lut;
        #pragma unroll
        for (int i = 0; i < 4; i++) {
            int idx = tid + i * 256;        // < 1024
            *(float4*)(S + S_LUT + idx * 4) = lv[idx];
        }
        if (tid < 128) {
            sc[tid]       = g_hn[0][rt + tid];
            sc[128 + tid] = g_hn[1][rs + tid];
            sc[256 + tid] = g_ln[0][rt + tid];
            sc[384 + tid] = g_ln[1][rs + tid];
            sc[512 + tid] = g_c [0][rt + tid];
            sc[640 + tid] = g_c [1][rs + tid];
        }
    }
    float w2b = __ldg(w2_b);
    __syncthreads();

    int wid  = tid >> 5;
    int lane = tid & 31;
    int g    = lane >> 2;       // 0..7
    int q    = lane & 3;        // 0..3
    int m0   = wid * 16;        // warp strip rows [m0, m0+16)

    // per-thread row scalars
    float ct0  = sc[512 + m0 + g],  ct1  = sc[512 + m0 + g + 8];
    float lnt0 = sc[256 + m0 + g],  lnt1 = sc[256 + m0 + g + 8];
    float hnt0 = sc[m0 + g],        hnt1 = sc[m0 + g + 8];

    // ============ Phase A: theta + l Grams -> tp[16][4] ============
    unsigned aT[4][4], aL[2][4];
    #pragma unroll
    for (int ks = 0; ks < 4; ks++) {
        const float* p0 = S + S_PT + (m0 + g) * 36 + ks * 8 + q;
        const float* p1 = S + S_PT + (m0 + g + 8) * 36 + ks * 8 + q;
        aT[ks][0] = ldsu(p0);     aT[ks][1] = ldsu(p1);
        aT[ks][2] = ldsu(p0 + 4); aT[ks][3] = ldsu(p1 + 4);
    }
    #pragma unroll
    for (int ks = 0; ks < 2; ks++) {
        const float* p0 = S + S_LT + (m0 + g) * 20 + ks * 8 + q;
        const float* p1 = S + S_LT + (m0 + g + 8) * 20 + ks * 8 + q;
        aL[ks][0] = ldsu(p0);     aL[ks][1] = ldsu(p1);
        aL[ks][2] = ldsu(p0 + 4); aL[ks][3] = ldsu(p1 + 4);
    }

    float tp[16][4];
    const float2* slut = (const float2*)(S + S_LUT);

    #pragma unroll
    for (int n = 0; n < 16; n++) {
        int n0 = n * 8;
        float dT[4] = {0.f, 0.f, 0.f, 0.f};
        #pragma unroll
        for (int ks = 0; ks < 4; ks++) {
            const float* bp = S + S_QS + (n0 + g) * 36 + ks * 8 + q;
            unsigned b[2] = { ldsu(bp), ldsu(bp + 4) };
            mma8(dT, aT[ks], b);
        }
        float dL[4] = {0.f, 0.f, 0.f, 0.f};
        #pragma unroll
        for (int ks = 0; ks < 2; ks++) {
            const float* bp = S + S_LS + (n0 + g) * 20 + ks * 8 + q;
            unsigned b[2] = { ldsu(bp), ldsu(bp + 4) };
            mma8(dL, aL[ks], b);
        }
        int c0 = n0 + 2 * q, c1 = c0 + 1;
        float cs0  = sc[640 + c0], cs1  = sc[640 + c1];
        float lns0 = sc[384 + c0], lns1 = sc[384 + c1];
        float ctv[4]  = { ct0, ct0, ct1, ct1 };
        float csv[4]  = { cs0, cs1, cs0, cs1 };
        float lntv[4] = { lnt0, lnt0, lnt1, lnt1 };
        float lnsv[4] = { lns0, lns1, lns0, lns1 };
        #pragma unroll
        for (int e = 0; e < 4; e++) {
            float a = w2b + ctv[e] + csv[e] + dT[e];
            float u = a * a;
            float Th = a * fmaf(u, fmaf(u, fmaf(u, -0.05396825397f,
                                 0.13333333333f), -0.33333333333f), 1.0f);
            float dl2 = fmaxf(fmaf(-2.f, dL[e], lntv[e] + lnsv[e]), 0.f);
            float t   = fminf(dl2 * LUTSCL, (float)(LUTN - 1));
            int   ix  = (int)t;
            float fr  = t - (float)ix;
            float2 lv = slut[ix];
            tp[n][e] = -Th * fmaf(fr, lv.y, lv.x);
        }
    }

    // ============ Phase B: h Gram (K=128) ============
    float acc[16][4];
    #pragma unroll
    for (int n = 0; n < 16; n++)
        #pragma unroll
        for (int e = 0; e < 4; e++) acc[n][e] = 0.f;

    #pragma unroll 4
    for (int ks = 0; ks < 16; ks++) {
        int k0 = ks * 8;
        const float* p0 = S + S_HT + (m0 + g) * 132 + k0 + q;
        const float* p1 = S + S_HT + (m0 + g + 8) * 132 + k0 + q;
        unsigned a[4] = { ldsu(p0), ldsu(p1), ldsu(p0 + 4), ldsu(p1 + 4) };
        #pragma unroll
        for (int n = 0; n < 16; n++) {
            const float* bp = S + S_HS + (n * 8 + g) * 132 + k0 + q;
            unsigned b[2] = { ldsu(bp), ldsu(bp + 4) };
            mma8(acc[n], a, b);
        }
    }

    // ============ epilogue ============
    {
        size_t orow0 = ((size_t)(bz * TT + t0 + m0 + g)) * TT + s0;
        size_t orow1 = orow0 + (size_t)8 * TT;
        #pragma unroll
        for (int n = 0; n < 16; n++) {
            int c0 = n * 8 + 2 * q;
            float hns0 = sc[128 + c0], hns1 = sc[128 + c0 + 1];
            float d0 = fmaxf(fmaf(-2.f, acc[n][0], hnt0 + hns0), 0.f) + EPS2;
            float d1 = fmaxf(fmaf(-2.f, acc[n][1], hnt0 + hns1), 0.f) + EPS2;
            float d2 = fmaxf(fmaf(-2.f, acc[n][2], hnt1 + hns0), 0.f) + EPS2;
            float d3 = fmaxf(fmaf(-2.f, acc[n][3], hnt1 + hns1), 0.f) + EPS2;
            float2 v0 = make_float2(tp[n][0] * rsqrtf(d0), tp[n][1] * rsqrtf(d1));
            float2 v1 = make_float2(tp[n][2] * rsqrtf(d2), tp[n][3] * rsqrtf(d3));
            *(float2*)(out + orow0 + c0) = v0;
            *(float2*)(out + orow1 + c0) = v1;
        }
    }
}

// ---------------------------------------------------------------------------
extern "C" void kernel_launch(void* const* d_in, const int* in_sizes, int n_in,
                              void* d_out, int out_size)
{
    (void)in_sizes; (void)n_in; (void)out_size;
    const float* h       = (const float*)d_in[0];
    const float* hsrc    = (const float*)d_in[1];
    const float* W_l     = (const float*)d_in[2];
    const float* W_theta = (const float*)d_in[3];
    const float* phi1_w  = (const float*)d_in[4];
    const float* phi1_b  = (const float*)d_in[5];
    const float* phi2_w  = (const float*)d_in[6];
    const float* phi2_b  = (const float*)d_in[7];
    const float* wq      = (const float*)d_in[8];
    const float* ws      = (const float*)d_in[9];
    const float* wd      = (const float*)d_in[10];
    const float* b1      = (const float*)d_in[11];
    const float* w2_w    = (const float*)d_in[12];
    const float* w2_b    = (const float*)d_in[13];
    float* out = (float*)d_out;

    cudaFuncSetAttribute(prep_kernel,
                         cudaFuncAttributeMaxDynamicSharedMemorySize, PREP_SMEM);
    cudaFuncSetAttribute(main_kernel,
                         cudaFuncAttributeMaxDynamicSharedMemorySize, MAIN_SMEM);

    prep_kernel<<<dim3(64, 3), 128, PREP_SMEM>>>(h, hsrc, W_l, W_theta,
                                                 wq, ws, wd, b1, w2_w,
                                                 phi1_w, phi1_b, phi2_w, phi2_b);
    main_kernel<<<dim3(4, 4, BB), 256, MAIN_SMEM>>>(h, hsrc, w2_b, out);
}